// round 15
// baseline (speedup 1.0000x reference)
#include <cuda_runtime.h>

#define NN 2048
#define BB 16
#define DD 8
#define OTILE 128          // 32 threads.x * 4 floats
#define ECHUNK 74
#define ESPLIT 28          // 28*74 = 2072 >= 2048 ; grid 16*28 = 448 = ~3/SM

// scratch (no allocs allowed)
__device__ float g_A[NN * DD * BB];              // [e][d*16+b]  (1 MB)
__device__ float g_partial[ESPLIT * BB * NN];    // [split][b][o] (3.5 MB)

// A[e][db] = Xd[db][e] * (Wshort[db][e] + 1)  via smem-tiled transpose.
__global__ __launch_bounds__(256)
void prep_A_t(const float* __restrict__ Xd, const float* __restrict__ Wshort) {
    __shared__ float tile[32][33];
    const int tx = threadIdx.x;            // 0..31
    const int ty = threadIdx.y;            // 0..7
    const int e_base  = blockIdx.x * 32;   // 64 tiles
    const int db_base = blockIdx.y * 32;   // 4 tiles

#pragma unroll
    for (int j = 0; j < 4; j++) {
        const int db = db_base + ty + j * 8;
        const int e  = e_base + tx;
        const int g  = db * NN + e;        // coalesced read
        tile[ty + j * 8][tx] = Xd[g] * (Wshort[g] + 1.0f);
    }
    __syncthreads();
#pragma unroll
    for (int j = 0; j < 4; j++) {
        const int e  = e_base + ty + j * 8;
        const int db = db_base + tx;
        g_A[e * (DD * BB) + db] = tile[tx][ty + j * 8];   // coalesced write
    }
}

__global__ __launch_bounds__(256, 3)
void delta_syn_main(const float* __restrict__ W,
                    const float* __restrict__ Wlong,
                    const float* __restrict__ dm,
                    const float* __restrict__ frac,
                    const float* __restrict__ signs_pre) {
    __shared__ float A_sm[ECHUNK * DD * BB];   // 37.9 KB

    const int tx    = threadIdx.x;             // 0..31
    const int ty    = threadIdx.y;             // 0..7  -> b pair
    const int tid   = ty * 32 + tx;
    const int o     = blockIdx.x * OTILE + tx * 4;
    const int split = blockIdx.y;
    const int e0    = split * ECHUNK;
    const int e1    = min(NN, e0 + ECHUNK);
    const int ecnt  = e1 - e0;

    // stage A[e0:e1][d][b] into smem (contiguous float4 copy; warp = one row)
    {
        const float4* src = reinterpret_cast<const float4*>(g_A + e0 * (DD * BB));
        float4* dst = reinterpret_cast<float4*>(A_sm);
        const int nvec = ecnt * (DD * BB) / 4;
        for (int i = tid; i < nvec; i += 256) dst[i] = src[i];
    }
    __syncthreads();

    float acc[2][4];
#pragma unroll
    for (int bi = 0; bi < 2; bi++)
#pragma unroll
        for (int oi = 0; oi < 4; oi++) acc[bi][oi] = 0.0f;

#pragma unroll 1
    for (int ee = 0; ee < ecnt; ee++) {
        const int e    = e0 + ee;
        const int base = e * NN + o;

        // ---- issue all global loads up front (MLP = 12 LDG.128) ----
        const float4 w4 = *reinterpret_cast<const float4*>(W + base);
        const float4 f4 = *reinterpret_cast<const float4*>(frac + base);
        const float  sp = __ldg(signs_pre + e);

        float4 dm4[DD];
#pragma unroll
        for (int d = 0; d < DD; d++)
            dm4[d] = *reinterpret_cast<const float4*>(dm + d * (NN * NN) + base);

        float4 wl4[2];
#pragma unroll
        for (int bi = 0; bi < 2; bi++) {
            const int b = ty * 2 + bi;
            wl4[bi] = *reinterpret_cast<const float4*>(Wlong + b * (NN * NN) + base);
        }

        // ---- P/Q from W, frac, sign ----
        const float s = (sp > 0.0f) ? 1.0f : ((sp < 0.0f) ? -1.0f : 0.0f);
        float wv[4] = {w4.x, w4.y, w4.z, w4.w};
        float fv[4] = {f4.x, f4.y, f4.z, f4.w};
        float P[4], Q[4];
#pragma unroll
        for (int oi = 0; oi < 4; oi++) {
            const bool m = wv[oi] > 0.0f;
            P[oi] = m ? s * wv[oi] * (1.0f - fv[oi]) : 0.0f;
            Q[oi] = m ? s * fv[oi] : 0.0f;
        }

        // ---- S[bi][oi] = sum_d A[d][b] * dm[d][o]  (A via LDS.64 broadcast) ----
        float S[2][4];
#pragma unroll
        for (int bi = 0; bi < 2; bi++)
#pragma unroll
            for (int oi = 0; oi < 4; oi++) S[bi][oi] = 0.0f;

#pragma unroll
        for (int d = 0; d < DD; d++) {
            const float2 a2 = *reinterpret_cast<const float2*>(
                A_sm + ee * (DD * BB) + d * BB + ty * 2);
            const float av[2] = {a2.x, a2.y};
            const float dv[4] = {dm4[d].x, dm4[d].y, dm4[d].z, dm4[d].w};
#pragma unroll
            for (int bi = 0; bi < 2; bi++)
#pragma unroll
                for (int oi = 0; oi < 4; oi++)
                    S[bi][oi] = fmaf(av[bi], dv[oi], S[bi][oi]);
        }

        // ---- acc += (P + Q*Wlong) * S ----
#pragma unroll
        for (int bi = 0; bi < 2; bi++) {
            const float wlv[4] = {wl4[bi].x, wl4[bi].y, wl4[bi].z, wl4[bi].w};
#pragma unroll
            for (int oi = 0; oi < 4; oi++) {
                const float t = fmaf(Q[oi], wlv[oi], P[oi]);
                acc[bi][oi] = fmaf(t, S[bi][oi], acc[bi][oi]);
            }
        }
    }

    // write deterministic partials
#pragma unroll
    for (int bi = 0; bi < 2; bi++) {
        const int b = ty * 2 + bi;
        float4 v = make_float4(acc[bi][0], acc[bi][1], acc[bi][2], acc[bi][3]);
        *reinterpret_cast<float4*>(g_partial + (split * BB + b) * NN + o) = v;
    }
}

// float4 per quad; 28 splits = 4 lanes x 7; butterfly combine.
__global__ __launch_bounds__(256)
void reduce_partials(float* __restrict__ out) {
    const int t = blockIdx.x * blockDim.x + threadIdx.x;   // 0 .. 32767
    const int q = t >> 2;                                  // float4 output idx
    const int p = t & 3;                                   // partition id
    const float4* gp = reinterpret_cast<const float4*>(g_partial);
    float sx = 0.f, sy = 0.f, sz = 0.f, sw = 0.f;
#pragma unroll
    for (int k = 0; k < 7; k++) {
        const int sp = p * 7 + k;
        const float4 v = gp[sp * (BB * NN / 4) + q];
        sx += v.x; sy += v.y; sz += v.z; sw += v.w;
    }
#pragma unroll
    for (int m = 1; m <= 2; m <<= 1) {
        sx += __shfl_xor_sync(0xffffffffu, sx, m);
        sy += __shfl_xor_sync(0xffffffffu, sy, m);
        sz += __shfl_xor_sync(0xffffffffu, sz, m);
        sw += __shfl_xor_sync(0xffffffffu, sw, m);
    }
    if (p == 0)
        reinterpret_cast<float4*>(out)[q] = make_float4(sx, sy, sz, sw);
}

extern "C" void kernel_launch(void* const* d_in, const int* in_sizes, int n_in,
                              void* d_out, int out_size) {
    const float* W         = (const float*)d_in[0];  // (N,N)
    const float* Wlong     = (const float*)d_in[1];  // (B,N,N)
    const float* Wshort    = (const float*)d_in[2];  // (D,B,N)
    const float* Xd        = (const float*)d_in[3];  // (D,B,N)
    const float* delaymap  = (const float*)d_in[4];  // (D,N,N)
    const float* STDP_frac = (const float*)d_in[5];  // (N,N)
    const float* signs_pre = (const float*)d_in[6];  // (N,)
    float* out = (float*)d_out;                      // (B,N)

    dim3 tgrid(NN / 32, (DD * BB) / 32);   // (64, 4)
    dim3 tblock(32, 8);
    prep_A_t<<<tgrid, tblock>>>(Xd, Wshort);

    dim3 grid(NN / OTILE, ESPLIT);   // (16, 28) = 448 blocks ~ 3/SM
    dim3 block(32, 8);
    delta_syn_main<<<grid, block>>>(W, Wlong, delaymap, STDP_frac, signs_pre);

    reduce_partials<<<(4 * BB * NN / 4) / 256, 256>>>(out);   // 128 blocks
}

// round 16
// speedup vs baseline: 1.0891x; 1.0891x over previous
#include <cuda_runtime.h>

#define NN 2048
#define BB 16
#define DD 8
#define OTILE 256          // 64 threads.x * 4 floats
#define ECHUNK 56
#define ESPLIT 37          // 37*56 = 2072 >= 2048 ; 8*37 = 296 blocks = 2/SM

// scratch (no allocs allowed)
__device__ float g_A[NN * DD * BB];              // [e][d*16+b]  (1 MB)
__device__ float g_partial[ESPLIT * BB * NN];    // [split][b][o] (4.6 MB)

// A[e][db] = Xd[db][e] * (Wshort[db][e] + 1)  via smem-tiled transpose.
__global__ __launch_bounds__(256)
void prep_A_t(const float* __restrict__ Xd, const float* __restrict__ Wshort) {
    __shared__ float tile[32][33];
    const int tx = threadIdx.x;            // 0..31
    const int ty = threadIdx.y;            // 0..7
    const int e_base  = blockIdx.x * 32;   // 64 tiles
    const int db_base = blockIdx.y * 32;   // 4 tiles

#pragma unroll
    for (int j = 0; j < 4; j++) {
        const int db = db_base + ty + j * 8;
        const int e  = e_base + tx;
        const int g  = db * NN + e;        // coalesced read
        tile[ty + j * 8][tx] = Xd[g] * (Wshort[g] + 1.0f);
    }
    __syncthreads();
#pragma unroll
    for (int j = 0; j < 4; j++) {
        const int e  = e_base + ty + j * 8;
        const int db = db_base + tx;
        g_A[e * (DD * BB) + db] = tile[tx][ty + j * 8];   // coalesced write
    }
}

__global__ __launch_bounds__(256, 2)
void delta_syn_main(const float* __restrict__ W,
                    const float* __restrict__ Wlong,
                    const float* __restrict__ dm,
                    const float* __restrict__ frac,
                    const float* __restrict__ signs_pre) {
    __shared__ float A_sm[ECHUNK * DD * BB];   // 28 KB

    const int tx    = threadIdx.x;             // 0..63
    const int ty    = threadIdx.y;             // 0..3  -> b group of 4
    const int tid   = ty * 64 + tx;
    const int o     = blockIdx.x * OTILE + tx * 4;
    const int split = blockIdx.y;
    const int e0    = split * ECHUNK;
    const int e1    = min(NN, e0 + ECHUNK);
    const int ecnt  = e1 - e0;

    // stage A[e0:e1][d][b] into smem (contiguous float4 copy)
    {
        const float4* src = reinterpret_cast<const float4*>(g_A + e0 * (DD * BB));
        float4* dst = reinterpret_cast<float4*>(A_sm);
        const int nvec = ecnt * (DD * BB) / 4;
        for (int i = tid; i < nvec; i += 256) dst[i] = src[i];
    }
    __syncthreads();

    float acc[4][4];
#pragma unroll
    for (int bi = 0; bi < 4; bi++)
#pragma unroll
        for (int oi = 0; oi < 4; oi++) acc[bi][oi] = 0.0f;

#pragma unroll 1
    for (int ee = 0; ee < ecnt; ee++) {
        const int e    = e0 + ee;
        const int base = e * NN + o;

        // ---- issue all global loads up front (MLP) ----
        const float4 w4 = *reinterpret_cast<const float4*>(W + base);
        const float4 f4 = *reinterpret_cast<const float4*>(frac + base);
        const float  sp = __ldg(signs_pre + e);

        float4 dm4[DD];
#pragma unroll
        for (int d = 0; d < DD; d++)
            dm4[d] = *reinterpret_cast<const float4*>(dm + d * (NN * NN) + base);

        float4 wl4[4];
#pragma unroll
        for (int bi = 0; bi < 4; bi++) {
            const int b = ty * 4 + bi;
            wl4[bi] = *reinterpret_cast<const float4*>(Wlong + b * (NN * NN) + base);
        }

        // ---- P/Q from W, frac, sign ----
        const float s = (sp > 0.0f) ? 1.0f : ((sp < 0.0f) ? -1.0f : 0.0f);
        float wv[4] = {w4.x, w4.y, w4.z, w4.w};
        float fv[4] = {f4.x, f4.y, f4.z, f4.w};
        float P[4], Q[4];
#pragma unroll
        for (int oi = 0; oi < 4; oi++) {
            const bool m = wv[oi] > 0.0f;
            P[oi] = m ? s * wv[oi] * (1.0f - fv[oi]) : 0.0f;
            Q[oi] = m ? s * fv[oi] : 0.0f;
        }

        // ---- S[bi][oi] = sum_d A[d][b] * dm[d][o] ----
        float S[4][4];
#pragma unroll
        for (int bi = 0; bi < 4; bi++)
#pragma unroll
            for (int oi = 0; oi < 4; oi++) S[bi][oi] = 0.0f;

#pragma unroll
        for (int d = 0; d < DD; d++) {
            const float4 a4 = *reinterpret_cast<const float4*>(
                A_sm + ee * (DD * BB) + d * BB + ty * 4);
            const float av[4] = {a4.x, a4.y, a4.z, a4.w};
            const float dv[4] = {dm4[d].x, dm4[d].y, dm4[d].z, dm4[d].w};
#pragma unroll
            for (int bi = 0; bi < 4; bi++)
#pragma unroll
                for (int oi = 0; oi < 4; oi++)
                    S[bi][oi] = fmaf(av[bi], dv[oi], S[bi][oi]);
        }

        // ---- acc += (P + Q*Wlong) * S ----
#pragma unroll
        for (int bi = 0; bi < 4; bi++) {
            const float wlv[4] = {wl4[bi].x, wl4[bi].y, wl4[bi].z, wl4[bi].w};
#pragma unroll
            for (int oi = 0; oi < 4; oi++) {
                const float t = fmaf(Q[oi], wlv[oi], P[oi]);
                acc[bi][oi] = fmaf(t, S[bi][oi], acc[bi][oi]);
            }
        }
    }

    // write deterministic partials
#pragma unroll
    for (int bi = 0; bi < 4; bi++) {
        const int b = ty * 4 + bi;
        float4 v = make_float4(acc[bi][0], acc[bi][1], acc[bi][2], acc[bi][3]);
        *reinterpret_cast<float4*>(g_partial + (split * BB + b) * NN + o) = v;
    }
}

// 8-way split (37 = 5*5 + 3*4) x float4; 3 butterfly rounds; lane p==0 stores.
__global__ __launch_bounds__(256)
void reduce_partials(float* __restrict__ out) {
    const int t = blockIdx.x * blockDim.x + threadIdx.x;   // 0 .. 65535
    const int q = t >> 3;                                  // float4 output idx
    const int p = t & 7;                                   // partition id
    const int s0  = (p < 5) ? p * 5 : 25 + (p - 5) * 4;
    const int cnt = (p < 5) ? 5 : 4;
    const float4* gp = reinterpret_cast<const float4*>(g_partial);
    float sx = 0.f, sy = 0.f, sz = 0.f, sw = 0.f;
#pragma unroll
    for (int k = 0; k < 5; k++) {
        if (k < cnt) {
            const float4 v = gp[(s0 + k) * (BB * NN / 4) + q];
            sx += v.x; sy += v.y; sz += v.z; sw += v.w;
        }
    }
#pragma unroll
    for (int m = 1; m <= 4; m <<= 1) {
        sx += __shfl_xor_sync(0xffffffffu, sx, m);
        sy += __shfl_xor_sync(0xffffffffu, sy, m);
        sz += __shfl_xor_sync(0xffffffffu, sz, m);
        sw += __shfl_xor_sync(0xffffffffu, sw, m);
    }
    if (p == 0)
        reinterpret_cast<float4*>(out)[q] = make_float4(sx, sy, sz, sw);
}

extern "C" void kernel_launch(void* const* d_in, const int* in_sizes, int n_in,
                              void* d_out, int out_size) {
    const float* W         = (const float*)d_in[0];  // (N,N)
    const float* Wlong     = (const float*)d_in[1];  // (B,N,N)
    const float* Wshort    = (const float*)d_in[2];  // (D,B,N)
    const float* Xd        = (const float*)d_in[3];  // (D,B,N)
    const float* delaymap  = (const float*)d_in[4];  // (D,N,N)
    const float* STDP_frac = (const float*)d_in[5];  // (N,N)
    const float* signs_pre = (const float*)d_in[6];  // (N,)
    float* out = (float*)d_out;                      // (B,N)

    dim3 tgrid(NN / 32, (DD * BB) / 32);   // (64, 4)
    dim3 tblock(32, 8);
    prep_A_t<<<tgrid, tblock>>>(Xd, Wshort);

    dim3 grid(NN / OTILE, ESPLIT);   // (8, 37) = 296 blocks = 2/SM
    dim3 block(64, 4);
    delta_syn_main<<<grid, block>>>(W, Wlong, delaymap, STDP_frac, signs_pre);

    reduce_partials<<<(8 * BB * NN / 4) / 256, 256>>>(out);   // 256 blocks
}

// round 17
// speedup vs baseline: 1.0937x; 1.0042x over previous
#include <cuda_runtime.h>
#include <cstdint>

#define NN 2048
#define BB 16
#define DD 8
#define OTILE 256          // 64 threads.x * 4 floats
#define ECHUNK 56
#define ESPLIT 37          // 37*56 = 2072 >= 2048 ; 8*37 = 296 blocks = 2/SM

// scratch (no allocs allowed)
__device__ float g_A[NN * DD * BB];              // [e][d*16+b]  (1 MB)
__device__ float g_partial[ESPLIT * BB * NN];    // [split][b][o] (4.6 MB)

// ---- f32x2 packed-math helpers (sm_103a FFMA2 path, PTX-only) ----
__device__ __forceinline__ unsigned long long pack2(float lo, float hi) {
    unsigned long long r;
    asm("mov.b64 %0, {%1, %2};" : "=l"(r) : "f"(lo), "f"(hi));
    return r;
}
__device__ __forceinline__ unsigned long long rep2(float v) {
    unsigned long long r;
    asm("mov.b64 %0, {%1, %1};" : "=l"(r) : "f"(v));
    return r;
}
__device__ __forceinline__ unsigned long long fma2(unsigned long long a,
                                                   unsigned long long b,
                                                   unsigned long long c) {
    unsigned long long d;
    asm("fma.rn.f32x2 %0, %1, %2, %3;" : "=l"(d) : "l"(a), "l"(b), "l"(c));
    return d;
}
__device__ __forceinline__ float2 unpack2(unsigned long long v) {
    float2 f;
    asm("mov.b64 {%0, %1}, %2;" : "=f"(f.x), "=f"(f.y) : "l"(v));
    return f;
}

// A[e][db] = Xd[db][e] * (Wshort[db][e] + 1)  via smem-tiled transpose.
__global__ __launch_bounds__(256)
void prep_A_t(const float* __restrict__ Xd, const float* __restrict__ Wshort) {
    __shared__ float tile[32][33];
    const int tx = threadIdx.x;            // 0..31
    const int ty = threadIdx.y;            // 0..7
    const int e_base  = blockIdx.x * 32;   // 64 tiles
    const int db_base = blockIdx.y * 32;   // 4 tiles

#pragma unroll
    for (int j = 0; j < 4; j++) {
        const int db = db_base + ty + j * 8;
        const int e  = e_base + tx;
        const int g  = db * NN + e;        // coalesced read
        tile[ty + j * 8][tx] = Xd[g] * (Wshort[g] + 1.0f);
    }
    __syncthreads();
#pragma unroll
    for (int j = 0; j < 4; j++) {
        const int e  = e_base + ty + j * 8;
        const int db = db_base + tx;
        g_A[e * (DD * BB) + db] = tile[tx][ty + j * 8];   // coalesced write
    }
}

__global__ __launch_bounds__(256, 2)
void delta_syn_main(const float* __restrict__ W,
                    const float* __restrict__ Wlong,
                    const float* __restrict__ dm,
                    const float* __restrict__ frac,
                    const float* __restrict__ signs_pre) {
    __shared__ float A_sm[ECHUNK * DD * BB];   // 28 KB

    const int tx    = threadIdx.x;             // 0..63
    const int ty    = threadIdx.y;             // 0..3  -> b group of 4
    const int tid   = ty * 64 + tx;
    const int o     = blockIdx.x * OTILE + tx * 4;
    const int split = blockIdx.y;
    const int e0    = split * ECHUNK;
    const int e1    = min(NN, e0 + ECHUNK);
    const int ecnt  = e1 - e0;

    // stage A[e0:e1][d][b] into smem (contiguous float4 copy)
    {
        const float4* src = reinterpret_cast<const float4*>(g_A + e0 * (DD * BB));
        float4* dst = reinterpret_cast<float4*>(A_sm);
        const int nvec = ecnt * (DD * BB) / 4;
        for (int i = tid; i < nvec; i += 256) dst[i] = src[i];
    }
    __syncthreads();

    unsigned long long acc2[4][2];
#pragma unroll
    for (int bi = 0; bi < 4; bi++) { acc2[bi][0] = 0ull; acc2[bi][1] = 0ull; }

#pragma unroll 1
    for (int ee = 0; ee < ecnt; ee++) {
        const int e    = e0 + ee;
        const int base = e * NN + o;

        // ---- issue all global loads up front (MLP, plain LDG.128) ----
        const float4 w4 = *reinterpret_cast<const float4*>(W + base);
        const float4 f4 = *reinterpret_cast<const float4*>(frac + base);
        const float  sp = __ldg(signs_pre + e);

        ulonglong2 dm2[DD];                 // o-pairs packed for free
#pragma unroll
        for (int d = 0; d < DD; d++)
            dm2[d] = *reinterpret_cast<const ulonglong2*>(dm + d * (NN * NN) + base);

        ulonglong2 wl2[4];
#pragma unroll
        for (int bi = 0; bi < 4; bi++) {
            const int b = ty * 4 + bi;
            wl2[bi] = *reinterpret_cast<const ulonglong2*>(Wlong + b * (NN * NN) + base);
        }

        // ---- P/Q from W, frac, sign (scalar, then packed) ----
        const float s = (sp > 0.0f) ? 1.0f : ((sp < 0.0f) ? -1.0f : 0.0f);
        const float wv[4] = {w4.x, w4.y, w4.z, w4.w};
        const float fv[4] = {f4.x, f4.y, f4.z, f4.w};
        float P[4], Q[4];
#pragma unroll
        for (int oi = 0; oi < 4; oi++) {
            const bool m = wv[oi] > 0.0f;
            P[oi] = m ? s * wv[oi] * (1.0f - fv[oi]) : 0.0f;
            Q[oi] = m ? s * fv[oi] : 0.0f;
        }
        const unsigned long long P2[2] = {pack2(P[0], P[1]), pack2(P[2], P[3])};
        const unsigned long long Q2[2] = {pack2(Q[0], Q[1]), pack2(Q[2], Q[3])};

        // ---- S2[bi][p] = sum_d A[d][b] * dm[d][o-pair p]  (FFMA2) ----
        unsigned long long S2[4][2];
#pragma unroll
        for (int bi = 0; bi < 4; bi++) { S2[bi][0] = 0ull; S2[bi][1] = 0ull; }

#pragma unroll
        for (int d = 0; d < DD; d++) {
            const float4 a4 = *reinterpret_cast<const float4*>(
                A_sm + ee * (DD * BB) + d * BB + ty * 4);
            const unsigned long long ar[4] =
                {rep2(a4.x), rep2(a4.y), rep2(a4.z), rep2(a4.w)};
#pragma unroll
            for (int bi = 0; bi < 4; bi++) {
                S2[bi][0] = fma2(ar[bi], dm2[d].x, S2[bi][0]);
                S2[bi][1] = fma2(ar[bi], dm2[d].y, S2[bi][1]);
            }
        }

        // ---- acc += (P + Q*Wlong) * S  (FFMA2) ----
#pragma unroll
        for (int bi = 0; bi < 4; bi++) {
            const unsigned long long t0 = fma2(Q2[0], wl2[bi].x, P2[0]);
            const unsigned long long t1 = fma2(Q2[1], wl2[bi].y, P2[1]);
            acc2[bi][0] = fma2(t0, S2[bi][0], acc2[bi][0]);
            acc2[bi][1] = fma2(t1, S2[bi][1], acc2[bi][1]);
        }
    }

    // write deterministic partials
#pragma unroll
    for (int bi = 0; bi < 4; bi++) {
        const int b = ty * 4 + bi;
        const float2 lo = unpack2(acc2[bi][0]);
        const float2 hi = unpack2(acc2[bi][1]);
        *reinterpret_cast<float4*>(g_partial + (split * BB + b) * NN + o) =
            make_float4(lo.x, lo.y, hi.x, hi.y);
    }
}

// 8-way split (37 = 5*5 + 3*4) x float4; 3 butterfly rounds; lane p==0 stores.
__global__ __launch_bounds__(256)
void reduce_partials(float* __restrict__ out) {
    const int t = blockIdx.x * blockDim.x + threadIdx.x;   // 0 .. 65535
    const int q = t >> 3;                                  // float4 output idx
    const int p = t & 7;                                   // partition id
    const int s0  = (p < 5) ? p * 5 : 25 + (p - 5) * 4;
    const int cnt = (p < 5) ? 5 : 4;
    const float4* gp = reinterpret_cast<const float4*>(g_partial);
    float sx = 0.f, sy = 0.f, sz = 0.f, sw = 0.f;
#pragma unroll
    for (int k = 0; k < 5; k++) {
        if (k < cnt) {
            const float4 v = gp[(s0 + k) * (BB * NN / 4) + q];
            sx += v.x; sy += v.y; sz += v.z; sw += v.w;
        }
    }
#pragma unroll
    for (int m = 1; m <= 4; m <<= 1) {
        sx += __shfl_xor_sync(0xffffffffu, sx, m);
        sy += __shfl_xor_sync(0xffffffffu, sy, m);
        sz += __shfl_xor_sync(0xffffffffu, sz, m);
        sw += __shfl_xor_sync(0xffffffffu, sw, m);
    }
    if (p == 0)
        reinterpret_cast<float4*>(out)[q] = make_float4(sx, sy, sz, sw);
}

extern "C" void kernel_launch(void* const* d_in, const int* in_sizes, int n_in,
                              void* d_out, int out_size) {
    const float* W         = (const float*)d_in[0];  // (N,N)
    const float* Wlong     = (const float*)d_in[1];  // (B,N,N)
    const float* Wshort    = (const float*)d_in[2];  // (D,B,N)
    const float* Xd        = (const float*)d_in[3];  // (D,B,N)
    const float* delaymap  = (const float*)d_in[4];  // (D,N,N)
    const float* STDP_frac = (const float*)d_in[5];  // (N,N)
    const float* signs_pre = (const float*)d_in[6];  // (N,)
    float* out = (float*)d_out;                      // (B,N)

    dim3 tgrid(NN / 32, (DD * BB) / 32);   // (64, 4)
    dim3 tblock(32, 8);
    prep_A_t<<<tgrid, tblock>>>(Xd, Wshort);

    dim3 grid(NN / OTILE, ESPLIT);   // (8, 37) = 296 blocks = 2/SM
    dim3 block(64, 4);
    delta_syn_main<<<grid, block>>>(W, Wlong, delaymap, STDP_frac, signs_pre);

    reduce_partials<<<(8 * BB * NN / 4) / 256, 256>>>(out);   // 256 blocks
}